// round 2
// baseline (speedup 1.0000x reference)
#include <cuda_runtime.h>
#include <math.h>

#define BS 8
#define NP 2048
#define CD 12
#define FD 2
#define DD 24
#define KS 16
#define RPB 8
#define TPB 256
#define MPT 8
#define CAP 256
#define FULLMASK 0xffffffffu

// smem layout (in 4-byte units):
//  s_A   : RPB*NP   = 16384 floats
//  s_q   : RPB*DD   = 192 floats
//  s_cv  : RPB*CAP  = 2048 floats
//  s_cm  : RPB*CAP  = 2048 ints
//  s_sel : RPB*KS   = 128 ints
#define SMEM_WORDS (RPB*NP + RPB*DD + RPB*CAP + RPB*CAP + RPB*KS)
#define SMEM_BYTES (SMEM_WORDS * 4)

// normalized features, d-major for coalesced m-loads: gFnT[b][d][m]
__device__ float gFnT[BS][DD][NP];

// ---------------------------------------------------------------------------
// prep: build normalized features (mimics reference fp32 arithmetic order) and
// write tgt_out (simple transposed copy of the flow slice).
// ---------------------------------------------------------------------------
__global__ void prep_kernel(const float* __restrict__ x, const int* __restrict__ flowp,
                            float* __restrict__ out) {
    int idx = blockIdx.x * blockDim.x + threadIdx.x;
    if (idx >= BS * NP) return;
    int b = idx >> 11;
    int n = idx & (NP - 1);
    int flow = flowp ? flowp[0] : 0;
    const float* xb = x + (size_t)b * (CD * FD * NP);

    float feats[DD];
#pragma unroll
    for (int f = 0; f < FD; f++)
#pragma unroll
        for (int c = 0; c < CD; c++)
            feats[f * CD + c] = xb[(c * FD + f) * NP + n];

    // norm = sqrt(sum(x*x)) with unfused mul/add (reduce of squares), + eps, IEEE div
    float ss = 0.f;
#pragma unroll
    for (int d = 0; d < DD; d++) ss = __fadd_rn(ss, __fmul_rn(feats[d], feats[d]));
    float denom = __fadd_rn(sqrtf(ss), 1e-8f);
#pragma unroll
    for (int d = 0; d < DD; d++)
        gFnT[b][d][n] = __fdiv_rn(feats[d], denom);

    // tgt_out[b][c][n] = x_c[b][c][flow][n]
    float* out2 = out + (size_t)BS * NP * KS * CD;
#pragma unroll
    for (int c = 0; c < CD; c++)
        out2[(b * CD + c) * NP + n] = xb[(c * FD + flow) * NP + n];
}

// ---------------------------------------------------------------------------
// main: per block (256 thr) handle 8 rows of one batch.
// Phase 1: register-blocked dot products (8 rows x 8 m per thread).
// Phase 2: warp-per-row exact top-16 with threshold + compaction.
// ---------------------------------------------------------------------------
__global__ void __launch_bounds__(TPB) main_kernel(const float* __restrict__ x,
                                                   const int* __restrict__ flowp,
                                                   float* __restrict__ out) {
    extern __shared__ float sm[];
    float* s_A   = sm;                          // [RPB][NP]
    float* s_q   = s_A + RPB * NP;              // [RPB][DD]
    float* s_cv  = s_q + RPB * DD;              // [RPB][CAP]
    int*   s_cm  = (int*)(s_cv + RPB * CAP);    // [RPB][CAP]
    int*   s_sel = s_cm + RPB * CAP;            // [RPB][KS]

    int blk = blockIdx.x;                 // BS * (NP/RPB) = 2048 blocks
    int b   = blk >> 8;                   // NP/RPB = 256 blocks per batch
    int n0  = (blk & 255) * RPB;
    int tid = threadIdx.x;

    // stage the 8 query rows into smem
    if (tid < RPB * DD) {
        int r = tid / DD, d = tid - r * DD;
        s_q[r * DD + d] = gFnT[b][d][n0 + r];
    }
    __syncthreads();

    // ---------------- phase 1: dots ----------------
    float acc[RPB][MPT];
#pragma unroll
    for (int r = 0; r < RPB; r++)
#pragma unroll
        for (int j = 0; j < MPT; j++) acc[r][j] = 0.f;

    for (int d = 0; d < DD; d++) {
        float fm[MPT];
#pragma unroll
        for (int j = 0; j < MPT; j++)
            fm[j] = gFnT[b][d][tid + TPB * j];   // coalesced
        float qv[RPB];
#pragma unroll
        for (int r = 0; r < RPB; r++) qv[r] = s_q[r * DD + d];  // broadcast
#pragma unroll
        for (int r = 0; r < RPB; r++)
#pragma unroll
            for (int j = 0; j < MPT; j++)
                acc[r][j] = fmaf(qv[r], fm[j], acc[r][j]);
    }

#pragma unroll
    for (int r = 0; r < RPB; r++)
#pragma unroll
        for (int j = 0; j < MPT; j++)
            s_A[r * NP + tid + TPB * j] = acc[r][j];
    __syncthreads();

    // ---------------- phase 2: warp-per-row exact top-16 ----------------
    int wid = tid >> 5, lane = tid & 31;
    int r = wid;
    int n = n0 + r;
    const float* Ar = s_A + r * NP;
    float* cv = s_cv + r * CAP;
    int*   cm = s_cm + r * CAP;
    int*   sel = s_sel + r * KS;

    // per-lane max over the row's 64 elements
    float lmax = -INFINITY;
    for (int j = 0; j < NP / 32; j++)
        lmax = fmaxf(lmax, Ar[lane + 32 * j]);

    // warp bitonic sort (descending) of the 32 lane maxima; T = 16th largest.
    // 16 lane-maxima >= T come from 16 distinct lanes => >= 16 elements >= T,
    // so the true top-16 all have value >= T.
    float sv = lmax;
#pragma unroll
    for (int k2 = 2; k2 <= 32; k2 <<= 1) {
#pragma unroll
        for (int j2 = k2 >> 1; j2 > 0; j2 >>= 1) {
            float o = __shfl_xor_sync(FULLMASK, sv, j2);
            bool up = ((lane & k2) == 0);
            bool lower = ((lane & j2) == 0);
            float mx = fmaxf(sv, o), mn = fminf(sv, o);
            sv = (up == lower) ? mx : mn;
        }
    }
    float T = __shfl_sync(FULLMASK, sv, 15);

    // compact survivors (v >= T) into a small list
    int cnt = 0;
    for (int j = 0; j < NP / 32; j++) {
        int mi = lane + 32 * j;
        float v = Ar[mi];
        bool p = (v >= T);
        unsigned bal = __ballot_sync(FULLMASK, p);
        if (p) {
            int pos = cnt + __popc(bal & ((1u << lane) - 1u));
            if (pos < CAP) { cv[pos] = v; cm[pos] = mi; }
        }
        cnt += __popc(bal);
    }
    __syncwarp();

    // exact ordered selection: (value desc, index asc), threshold-chained
    float pv = INFINITY; int pm = -1;
    if (cnt <= CAP) {
        for (int k = 0; k < KS; k++) {
            float bv = -INFINITY; int bm = 0x7fffffff;
            for (int i = lane; i < cnt; i += 32) {
                float v = cv[i]; int mi = cm[i];
                bool elig = (v < pv) || (v == pv && mi > pm);
                if (elig && ((v > bv) || (v == bv && mi < bm))) { bv = v; bm = mi; }
            }
#pragma unroll
            for (int off = 16; off > 0; off >>= 1) {
                float ov = __shfl_down_sync(FULLMASK, bv, off);
                int   om = __shfl_down_sync(FULLMASK, bm, off);
                if ((ov > bv) || (ov == bv && om < bm)) { bv = ov; bm = om; }
            }
            bv = __shfl_sync(FULLMASK, bv, 0);
            bm = __shfl_sync(FULLMASK, bm, 0);
            pv = bv; pm = bm;
            if (lane == 0) sel[k] = bm;
        }
    } else {
        // overflow fallback: exact selection over the full row (cold path)
        for (int k = 0; k < KS; k++) {
            float bv = -INFINITY; int bm = 0x7fffffff;
            for (int i = lane; i < NP; i += 32) {
                float v = Ar[i];
                bool elig = (v < pv) || (v == pv && i > pm);
                if (elig && ((v > bv) || (v == bv && i < bm))) { bv = v; bm = i; }
            }
#pragma unroll
            for (int off = 16; off > 0; off >>= 1) {
                float ov = __shfl_down_sync(FULLMASK, bv, off);
                int   om = __shfl_down_sync(FULLMASK, bm, off);
                if ((ov > bv) || (ov == bv && om < bm)) { bv = ov; bm = om; }
            }
            bv = __shfl_sync(FULLMASK, bv, 0);
            bm = __shfl_sync(FULLMASK, bm, 0);
            pv = bv; pm = bm;
            if (lane == 0) sel[k] = bm;
        }
    }
    __syncwarp();

    // gather: sx_c[b][n][k][c] = x_c[b][c][flow][sel[k]]
    int flow = flowp ? flowp[0] : 0;
    const float* xb = x + (size_t)b * (CD * FD * NP);
    float* o1 = out + (size_t)(b * NP + n) * (KS * CD);
    for (int t = lane; t < KS * CD; t += 32) {
        int k = t / CD;
        int c = t - k * CD;
        int m = sel[k];
        o1[t] = xb[(c * FD + flow) * NP + m];
    }
}

extern "C" void kernel_launch(void* const* d_in, const int* in_sizes, int n_in,
                              void* d_out, int out_size) {
    const float* x = (const float*)d_in[0];
    const int* flowp = (n_in >= 2) ? (const int*)d_in[1] : nullptr;
    float* out = (float*)d_out;

    prep_kernel<<<(BS * NP + 255) / 256, 256>>>(x, flowp, out);

    cudaFuncSetAttribute(main_kernel, cudaFuncAttributeMaxDynamicSharedMemorySize, SMEM_BYTES);
    main_kernel<<<BS * (NP / RPB), TPB, SMEM_BYTES>>>(x, flowp, out);
}